// round 1
// baseline (speedup 1.0000x reference)
#include <cuda_runtime.h>
#include <cstdint>

// Problem constants (from reference): B=2, S_LEN=2048 -> S=4096 tokens
#define S_TOK 4096
#define DIM   2048
#define NE    8
#define FF    5504
#define CAP   1024   // max(int(2*S/E*1.0), 4)

// ---------------- scratch (device globals; no dynamic allocation allowed) ---
__device__ float g_logits[S_TOK * NE];
__device__ int   g_idx1[S_TOK];
__device__ int   g_idx2[S_TOK];
__device__ float g_g1[S_TOK];
__device__ float g_g2[S_TOK];
__device__ int   g_slot1[S_TOK];
__device__ int   g_slot2[S_TOK];
__device__ int   g_tok4slot[NE * CAP];
__device__ int   g_count1[NE];
__device__ float g_me[NE];
__device__ float g_laux;
__device__ float g_xe[(size_t)NE * CAP * DIM];   //  64 MB
__device__ float g_t3[(size_t)NE * CAP * FF];    // 176 MB
__device__ float g_h [(size_t)NE * CAP * FF];    // 176 MB
__device__ float g_eo[(size_t)NE * CAP * DIM];   //  64 MB

// ---------------- packed f32x2 helpers (Blackwell FFMA2 path) --------------
__device__ __forceinline__ unsigned long long pack2(float lo, float hi) {
    unsigned long long r;
    asm("mov.b64 %0, {%1, %2};" : "=l"(r) : "f"(lo), "f"(hi));
    return r;
}
__device__ __forceinline__ void fma2(unsigned long long& d,
                                     unsigned long long a,
                                     unsigned long long b) {
    asm("fma.rn.f32x2 %0, %1, %2, %0;" : "+l"(d) : "l"(a), "l"(b));
}
__device__ __forceinline__ float2 unpack2(unsigned long long v) {
    float2 f;
    asm("mov.b64 {%0, %1}, %2;" : "=f"(f.x), "=f"(f.y) : "l"(v));
    return f;
}

// ---------------- init: reset per-call mutable scratch ----------------------
__global__ void k_init() {
    int i = blockIdx.x * blockDim.x + threadIdx.x;
    if (i < NE * CAP) g_tok4slot[i] = -1;
    if (i < NE) g_me[i] = 0.f;
}

// ---------------- gating logits: x[S,D] @ wg[D,E] ---------------------------
__global__ void k_logits(const float* __restrict__ x, const float* __restrict__ wg) {
    int s = blockIdx.x;
    float acc[NE];
#pragma unroll
    for (int e = 0; e < NE; e++) acc[e] = 0.f;
    const float* xr = x + (size_t)s * DIM;
    for (int j = threadIdx.x; j < DIM; j += blockDim.x) {
        float xv = xr[j];
        float4 w0 = *(const float4*)(wg + (size_t)j * NE);
        float4 w1v = *(const float4*)(wg + (size_t)j * NE + 4);
        acc[0] += xv * w0.x;  acc[1] += xv * w0.y;
        acc[2] += xv * w0.z;  acc[3] += xv * w0.w;
        acc[4] += xv * w1v.x; acc[5] += xv * w1v.y;
        acc[6] += xv * w1v.z; acc[7] += xv * w1v.w;
    }
#pragma unroll
    for (int off = 16; off; off >>= 1)
#pragma unroll
        for (int e = 0; e < NE; e++)
            acc[e] += __shfl_down_sync(0xffffffffu, acc[e], off);
    __shared__ float red[4][NE];
    int lane = threadIdx.x & 31, wp = threadIdx.x >> 5;
    if (lane == 0)
#pragma unroll
        for (int e = 0; e < NE; e++) red[wp][e] = acc[e];
    __syncthreads();
    if (threadIdx.x < NE) {
        float v = red[0][threadIdx.x] + red[1][threadIdx.x] +
                  red[2][threadIdx.x] + red[3][threadIdx.x];
        g_logits[(size_t)s * NE + threadIdx.x] = v;
    }
}

// ---------------- per-token softmax + top-2 ---------------------------------
__global__ void k_top2() {
    __shared__ float sme[NE];
    if (threadIdx.x < NE) sme[threadIdx.x] = 0.f;
    __syncthreads();
    int s = blockIdx.x * blockDim.x + threadIdx.x;
    float l[NE];
    float4 a = *(const float4*)(g_logits + (size_t)s * NE);
    float4 b = *(const float4*)(g_logits + (size_t)s * NE + 4);
    l[0] = a.x; l[1] = a.y; l[2] = a.z; l[3] = a.w;
    l[4] = b.x; l[5] = b.y; l[6] = b.z; l[7] = b.w;
    float mx = l[0];
#pragma unroll
    for (int e = 1; e < NE; e++) mx = fmaxf(mx, l[e]);
    float g[NE]; float sum = 0.f;
#pragma unroll
    for (int e = 0; e < NE; e++) { g[e] = __expf(l[e] - mx); sum += g[e]; }
    float inv = 1.f / sum;
    int i1 = 0; float b1 = l[0];
#pragma unroll
    for (int e = 1; e < NE; e++) if (l[e] > b1) { b1 = l[e]; i1 = e; }
    int i2 = 0; float b2 = -3.0e38f;
#pragma unroll
    for (int e = 0; e < NE; e++) if (e != i1 && l[e] > b2) { b2 = l[e]; i2 = e; }
    g_idx1[s] = i1;  g_idx2[s] = i2;
    g_g1[s] = g[i1] * inv;  g_g2[s] = g[i2] * inv;
#pragma unroll
    for (int e = 0; e < NE; e++) atomicAdd(&sme[e], g[e] * inv);
    __syncthreads();
    if (threadIdx.x < NE) atomicAdd(&g_me[threadIdx.x], sme[threadIdx.x]);
}

// ---------------- capacity scan: 1 warp per expert, ballot prefix-sum -------
__global__ void k_scan() {
    int lane = threadIdx.x & 31;
    int e = threadIdx.x >> 5;
    unsigned lmask = (1u << lane) - 1u;
    if (e < NE) {
        int c1 = 0;
        for (int s0 = 0; s0 < S_TOK; s0 += 32) {
            int s = s0 + lane;
            int m = (g_idx1[s] == e);
            unsigned bal = __ballot_sync(0xffffffffu, m);
            if (m) {
                int pos = c1 + __popc(bal & lmask);
                if (pos < CAP) { g_slot1[s] = pos; g_tok4slot[e * CAP + pos] = s; }
                else g_slot1[s] = -1;
            }
            c1 += __popc(bal);
        }
        if (lane == 0) g_count1[e] = c1;   // pre-drop count = exp_counts
        int c2 = c1;                        // loc2 offset uses pre-drop sum(mask1)
        for (int s0 = 0; s0 < S_TOK; s0 += 32) {
            int s = s0 + lane;
            int m = (g_idx2[s] == e);
            unsigned bal = __ballot_sync(0xffffffffu, m);
            if (m) {
                int pos = c2 + __popc(bal & lmask);
                if (pos < CAP) { g_slot2[s] = pos; g_tok4slot[e * CAP + pos] = s; }
                else g_slot2[s] = -1;
            }
            c2 += __popc(bal);
        }
    }
    __syncthreads();
    if (threadIdx.x == 0) {
        // l_aux = mean_e(me*ce) * E^2 = E * sum_e(me*ce)
        float acc = 0.f;
        for (int i = 0; i < NE; i++)
            acc += (g_me[i] / (float)S_TOK) * ((float)g_count1[i] / (float)S_TOK);
        g_laux = acc * (float)NE;
    }
}

// ---------------- dispatch: gather tokens into xe[E,C,D] --------------------
__global__ void k_dispatch(const float* __restrict__ x) {
    int slot = blockIdx.x;                 // 0..E*CAP-1
    int s = g_tok4slot[slot];
    float4* dst = (float4*)(g_xe + (size_t)slot * DIM);
    if (s >= 0) {
        const float4* src = (const float4*)(x + (size_t)s * DIM);
        for (int j = threadIdx.x; j < DIM / 4; j += blockDim.x) dst[j] = src[j];
    } else {
        float4 z = make_float4(0.f, 0.f, 0.f, 0.f);
        for (int j = threadIdx.x; j < DIM / 4; j += blockDim.x) dst[j] = z;
    }
}

// ---------------- grouped SGEMM (per-expert via blockIdx.z), f32x2 mainloop -
// C[e] = A[e] @ B[e];  EPI==1: C = silu(acc) * Aux  (for h = silu(xe@w1)*t3)
#define BM 128
#define BN 128
#define BK 16

template <int EPI>
__global__ void __launch_bounds__(256, 2)
sgemm(const float* __restrict__ Ag, const float* __restrict__ Bg,
      float* __restrict__ Cg, const float* __restrict__ Auxg,
      int M, int N, int K) {
    __shared__ float As[BK][BM];
    __shared__ float Bs[BK][BN];
    const int tid = threadIdx.x;
    const size_t eoffC = (size_t)blockIdx.z * M * N;
    const float* A = Ag + (size_t)blockIdx.z * M * K;
    const float* B = Bg + (size_t)blockIdx.z * K * N;
    float* C = Cg + eoffC;

    const int row0 = blockIdx.y * BM;
    const int col0 = blockIdx.x * BN;
    const int ty = tid >> 4;   // 0..15 -> 8 output rows each
    const int tx = tid & 15;   // 0..15 -> 8 output cols each

    unsigned long long acc[8][4];
#pragma unroll
    for (int i = 0; i < 8; i++)
#pragma unroll
        for (int j = 0; j < 4; j++) acc[i][j] = 0ull;

    for (int k0 = 0; k0 < K; k0 += BK) {
        // A tile: 128 rows x 16 cols = 512 float4, 2 per thread
#pragma unroll
        for (int it = 0; it < 2; it++) {
            int idx = it * 256 + tid;
            int ar = idx >> 2;
            int ac = (idx & 3) * 4;
            float4 av = *(const float4*)(A + (size_t)(row0 + ar) * K + k0 + ac);
            As[ac + 0][ar] = av.x;
            As[ac + 1][ar] = av.y;
            As[ac + 2][ar] = av.z;
            As[ac + 3][ar] = av.w;
        }
        // B tile: 16 rows x 128 cols = 512 float4, 2 per thread
#pragma unroll
        for (int it = 0; it < 2; it++) {
            int idx = it * 256 + tid;
            int br = idx >> 5;
            int bc = (idx & 31) * 4;
            *(float4*)&Bs[br][bc] =
                *(const float4*)(B + (size_t)(k0 + br) * N + col0 + bc);
        }
        __syncthreads();
#pragma unroll
        for (int k = 0; k < BK; k++) {
            float ar[8];
            *(float4*)&ar[0] = *(const float4*)&As[k][ty * 8];
            *(float4*)&ar[4] = *(const float4*)&As[k][ty * 8 + 4];
            ulonglong2 b01 = *(const ulonglong2*)&Bs[k][tx * 8];
            ulonglong2 b23 = *(const ulonglong2*)&Bs[k][tx * 8 + 4];
            unsigned long long bb0 = b01.x, bb1 = b01.y, bb2 = b23.x, bb3 = b23.y;
#pragma unroll
            for (int i = 0; i < 8; i++) {
                unsigned long long a2 = pack2(ar[i], ar[i]);
                fma2(acc[i][0], a2, bb0);
                fma2(acc[i][1], a2, bb1);
                fma2(acc[i][2], a2, bb2);
                fma2(acc[i][3], a2, bb3);
            }
        }
        __syncthreads();
    }

#pragma unroll
    for (int i = 0; i < 8; i++) {
        int r = row0 + ty * 8 + i;
        size_t off = (size_t)r * N + col0 + tx * 8;
        float o[8];
#pragma unroll
        for (int j2 = 0; j2 < 4; j2++) {
            float2 v = unpack2(acc[i][j2]);
            o[j2 * 2 + 0] = v.x;
            o[j2 * 2 + 1] = v.y;
        }
        if (EPI == 1) {
            const float* aux = Auxg + eoffC + off;
#pragma unroll
            for (int j = 0; j < 8; j++) {
                float xv = o[j];
                o[j] = (xv / (1.f + __expf(-xv))) * aux[j];   // silu(x)*aux
            }
        }
        *(float4*)(C + off) = *(float4*)&o[0];
        *(float4*)(C + off + 4) = *(float4*)&o[4];
    }
}

// ---------------- combine: out[s] = g1*eo[e1,c1] + g2*eo[e2,c2] -------------
__global__ void k_combine(float* __restrict__ out, int out_size) {
    int s = blockIdx.x;
    int sl1 = g_slot1[s], sl2 = g_slot2[s];
    float g1 = (sl1 >= 0) ? g_g1[s] : 0.f;
    float g2 = (sl2 >= 0) ? g_g2[s] : 0.f;
    float dn = fmaxf(g1 + g2, 1e-9f);
    g1 /= dn; g2 /= dn;
    const float4* r1 = (sl1 >= 0)
        ? (const float4*)(g_eo + ((size_t)g_idx1[s] * CAP + sl1) * DIM) : nullptr;
    const float4* r2 = (sl2 >= 0)
        ? (const float4*)(g_eo + ((size_t)g_idx2[s] * CAP + sl2) * DIM) : nullptr;
    float4* o = (float4*)(out + (size_t)s * DIM);
    for (int j = threadIdx.x; j < DIM / 4; j += blockDim.x) {
        float4 v = make_float4(0.f, 0.f, 0.f, 0.f);
        if (r1) { float4 t = r1[j]; v.x += g1 * t.x; v.y += g1 * t.y; v.z += g1 * t.z; v.w += g1 * t.w; }
        if (r2) { float4 t = r2[j]; v.x += g2 * t.x; v.y += g2 * t.y; v.z += g2 * t.z; v.w += g2 * t.w; }
        o[j] = v;
    }
    // auxiliary outputs (l_aux, exp_counts) if the output buffer carries them
    if (s == 0) {
        size_t base = (size_t)S_TOK * DIM;
        if ((size_t)out_size > base && threadIdx.x == 0) out[base] = g_laux;
        if ((size_t)out_size >= base + 1 + NE && threadIdx.x >= 1 && threadIdx.x <= NE)
            out[base + threadIdx.x] = (float)g_count1[threadIdx.x - 1];
    }
}

// ---------------- launch -----------------------------------------------------
extern "C" void kernel_launch(void* const* d_in, const int* in_sizes, int n_in,
                              void* d_out, int out_size) {
    (void)in_sizes; (void)n_in;
    const float* x  = (const float*)d_in[0];   // hidden_states [B,S_LEN,D]
    const float* wg = (const float*)d_in[1];   // [D,E]
    const float* w1 = (const float*)d_in[2];   // [E,D,F]
    const float* w3 = (const float*)d_in[3];   // [E,D,F]
    const float* w2 = (const float*)d_in[4];   // [E,F,D]
    float* out = (float*)d_out;

    void *p_xe, *p_t3, *p_h, *p_eo;
    cudaGetSymbolAddress(&p_xe, g_xe);
    cudaGetSymbolAddress(&p_t3, g_t3);
    cudaGetSymbolAddress(&p_h,  g_h);
    cudaGetSymbolAddress(&p_eo, g_eo);

    k_init<<<(NE * CAP + 255) / 256, 256>>>();
    k_logits<<<S_TOK, 128>>>(x, wg);
    k_top2<<<S_TOK / 256, 256>>>();
    k_scan<<<1, 256>>>();
    k_dispatch<<<NE * CAP, 256>>>(x);

    dim3 grid1(FF / BN, CAP / BM, NE);   // (43, 8, 8)
    sgemm<0><<<grid1, 256>>>((const float*)p_xe, w3, (float*)p_t3, nullptr,
                             CAP, FF, DIM);
    sgemm<1><<<grid1, 256>>>((const float*)p_xe, w1, (float*)p_h,
                             (const float*)p_t3, CAP, FF, DIM);
    dim3 grid2(DIM / BN, CAP / BM, NE);  // (16, 8, 8)
    sgemm<0><<<grid2, 256>>>((const float*)p_h, w2, (float*)p_eo, nullptr,
                             CAP, DIM, FF);

    k_combine<<<S_TOK, 256>>>(out, out_size);
}